// round 2
// baseline (speedup 1.0000x reference)
#include <cuda_runtime.h>
#include <math.h>

// Fixed problem shapes
#define BB    8
#define NA    5
#define NC    8
#define NH    192
#define NW    192
#define TT    50
#define ATTRS 15                 // 7 + NC
#define NHW   (NH*NW)            // 36864
#define CELLS (BB*NA*NHW)        // 1,474,560
#define NT    (BB*TT)            // 400
#define NIGN  (NT*NA)            // 2000

#define CPT       8                        // cells per dense thread
#define TPB       256
#define NB_DENSE  (CELLS/(CPT*TPB))        // 720 (exact)
#define NB_TOTAL  (NB_DENSE+1)             // 721
#define HASH_SZ   4096
#define HASH_MASK (HASH_SZ-1)

// ---- persistent device scratch (written every replay before being read) ----
__device__ double       g_partial[NB_DENSE];
__device__ double       g_corr[7];  // 0:noobjCorr 1:objconf 2..5:coords 6:ce
__device__ int          g_nObj, g_removed;
__device__ unsigned int g_ticket = 0;   // monotonic; reset by finisher

__device__ __forceinline__ float sp_fast(float v) {      // softplus ~= bce0
    return fmaxf(v, 0.f) + __logf(1.f + __expf(-fabsf(v)));
}
__device__ __forceinline__ float sigf(float v) {
    return 1.f / (1.f + __expf(-v));
}
__device__ __forceinline__ unsigned hash_cell(int cell) {
    return (((unsigned)cell * 2654435761u) >> 16) & HASH_MASK;
}

__global__ void __launch_bounds__(TPB, 4)
fused(const float* __restrict__ x,
      const float* __restrict__ tg,
      const float* __restrict__ anchors,
      float* __restrict__ out)
{
    __shared__ int    s_hash[HASH_SZ];
    __shared__ int    s_meta[NT];     // valid<<28 | best<<16 | gj<<8 | gi
    __shared__ int    s_label[NT];
    __shared__ float  s_fx[NT], s_fy[NT], s_tw[NT], s_th[NT], s_gw[NT], s_gh[NT];
    __shared__ double s_acc[7];
    __shared__ int    s_nObj, s_nIgn;
    __shared__ double s_warp[TPB/32];
    __shared__ float  s_anchor[2*NA];
    __shared__ int    s_isLast;

    const int tid = threadIdx.x;
    const int bid = blockIdx.x;

    if (bid < NB_DENSE) {
        // ================= dense: sum softplus over conf channel =================
        int t0 = (bid * TPB + tid) * CPT;
        int i0 = t0 % NW;
        int j  = (t0 / NW) % NH;
        int ba = t0 / NHW;
        const float* p = x + ((size_t)ba * ATTRS + 6) * NHW + (size_t)j * NW + i0;
        float4 a = *(const float4*)p;
        float4 b = *(const float4*)(p + 4);
        double local = (double)(sp_fast(a.x) + sp_fast(a.y) + sp_fast(a.z) + sp_fast(a.w))
                     + (double)(sp_fast(b.x) + sp_fast(b.y) + sp_fast(b.z) + sp_fast(b.w));
        #pragma unroll
        for (int o = 16; o; o >>= 1) local += __shfl_down_sync(0xffffffffu, local, o);
        if ((tid & 31) == 0) s_warp[tid >> 5] = local;
        __syncthreads();
        if (tid < TPB/32) {
            double v = s_warp[tid];
            #pragma unroll
            for (int o = TPB/64; o; o >>= 1) v += __shfl_down_sync(0xffu, v, o);
            if (tid == 0) g_partial[bid] = v;
        }
    } else {
        // ================= special block: targets + sparse corrections =================
        for (int i = tid; i < HASH_SZ; i += TPB) s_hash[i] = -1;
        if (tid < 7) s_acc[tid] = 0.0;
        if (tid == 0) { s_nObj = 0; s_nIgn = 0; }
        if (tid < 2*NA) s_anchor[tid] = anchors[tid];
        __syncthreads();

        // phase 0: per-target precompute
        for (int t = tid; t < NT; t += TPB) {
            const float* r = tg + (size_t)t * 5;
            float r0 = r[0], r1 = r[1], r2 = r[2], r3 = r[3], r4 = r[4];
            int valid = ((r0 + r1 + r2 + r3 + r4) != 0.f);
            float gx = r1 * NW, gy = r2 * NH, gw = r3 * NW, gh = r4 * NH;
            int gi = (int)floorf(gx), gj = (int)floorf(gy);
            float bestIou = -1.f; int best = 0; float awb = 1.f, ahb = 1.f;
            #pragma unroll
            for (int a = 0; a < NA; a++) {
                float aw = s_anchor[2*a], ah = s_anchor[2*a+1];
                float inter = fminf(gw, aw) * fminf(gh, ah);
                float iou   = inter / (gw * gh + aw * ah - inter);
                if (iou > bestIou) { bestIou = iou; best = a; awb = aw; ahb = ah; }
            }
            s_meta[t]  = (valid << 28) | (best << 16) | (gj << 8) | gi;
            s_label[t] = (int)r0;
            s_fx[t] = gx - floorf(gx);
            s_fy[t] = gy - floorf(gy);
            s_tw[t] = logf(gw / awb + 1e-16f);
            s_th[t] = logf(gh / ahb + 1e-16f);
            s_gw[t] = gw; s_gh[t] = gh;
        }
        __syncthreads();

        // phase 1: winners (last-write-wins) -> hash insert + obj-cell corrections
        for (int t = tid; t < NT; t += TPB) {
            int meta = s_meta[t];
            if (!(meta >> 28)) continue;
            int b = t / TT;
            bool winner = true;
            int tEnd = (b + 1) * TT;
            for (int t2 = t + 1; t2 < tEnd; t2++)
                if (s_meta[t2] == meta) { winner = false; break; }
            if (!winner) continue;

            int best = (meta >> 16) & 0xff, gj = (meta >> 8) & 0xff, gi = meta & 0xff;
            int cell = ((b * NA + best) * NH + gj) * NW + gi;
            unsigned h = hash_cell(cell);
            while (atomicCAS(&s_hash[h], -1, cell) != -1) h = (h + 1) & HASH_MASK;
            atomicAdd(&s_nObj, 1);

            size_t base = (size_t)(b * NA + best) * ATTRS * NHW + (size_t)gj * NW + gi;
            float x0 = x[base];
            float x1 = x[base + (size_t)NHW];
            float x2 = x[base + 2 * (size_t)NHW];
            float x3 = x[base + 3 * (size_t)NHW];
            float xc = x[base + 6 * (size_t)NHW];

            float dx = sigf(x0) - s_fx[t];
            float dy = sigf(x1) - s_fy[t];
            float dw = x2 - s_tw[t];
            float dh = x3 - s_th[t];
            atomicAdd(&s_acc[2], (double)(dx * dx));
            atomicAdd(&s_acc[3], (double)(dy * dy));
            atomicAdd(&s_acc[4], (double)(dw * dw));
            atomicAdd(&s_acc[5], (double)(dh * dh));
            atomicAdd(&s_acc[1], (double)sp_fast(-xc));   // -log p (tconf=1 bce)
            atomicAdd(&s_acc[0], -(double)sp_fast(xc));   // remove bce0 from noobj sum

            // class CE: log_softmax over sigmoid(logits)
            float sv[NC]; float m = -1e30f;
            #pragma unroll
            for (int c = 0; c < NC; c++) {
                sv[c] = sigf(x[base + (size_t)(7 + c) * NHW]);
                m = fmaxf(m, sv[c]);
            }
            float sum = 0.f;
            #pragma unroll
            for (int c = 0; c < NC; c++) sum += __expf(sv[c] - m);
            float ce = m + __logf(sum) - sv[s_label[t]];
            atomicAdd(&s_acc[6], (double)ce);
        }
        __syncthreads();   // all obj cells in hash before ignore probes

        // phase 2: ignore cells (iou > 0.6), dedup via hash; obj beats ignore
        for (int k = tid; k < NIGN; k += TPB) {
            int t = k / NA, a = k % NA;
            int meta = s_meta[t];
            if (!(meta >> 28)) continue;
            float aw = s_anchor[2*a], ah = s_anchor[2*a+1];
            float gw = s_gw[t], gh = s_gh[t];
            float inter = fminf(gw, aw) * fminf(gh, ah);
            float iou   = inter / (gw * gh + aw * ah - inter);
            if (!(iou > 0.6f)) continue;
            int b = t / TT, gj = (meta >> 8) & 0xff, gi = meta & 0xff;
            int cell = ((b * NA + a) * NH + gj) * NW + gi;
            unsigned h = hash_cell(cell);
            bool mine = false;
            while (true) {
                int prev = atomicCAS(&s_hash[h], -1, cell);
                if (prev == -1)   { mine = true; break; }
                if (prev == cell) break;                    // dup or obj cell
                h = (h + 1) & HASH_MASK;
            }
            if (!mine) continue;
            atomicAdd(&s_nIgn, 1);
            float xc = x[((size_t)(b * NA + a) * ATTRS + 6) * NHW + (size_t)gj * NW + gi];
            atomicAdd(&s_acc[0], -(double)sp_fast(xc));
        }
        __syncthreads();
        if (tid == 0) {
            #pragma unroll
            for (int i = 0; i < 7; i++) g_corr[i] = s_acc[i];
            g_nObj    = s_nObj;
            g_removed = s_nObj + s_nIgn;
        }
    }

    // ================= completion ticket + finalize by last block =================
    __syncthreads();
    if (tid == 0) {
        __threadfence();
        unsigned old = atomicAdd(&g_ticket, 1u);
        s_isLast = (old == (unsigned)(NB_TOTAL - 1));
        if (s_isLast) g_ticket = 0;   // replay-safe reset
    }
    __syncthreads();
    if (s_isLast) {
        double local = 0.0;
        for (int i = tid; i < NB_DENSE; i += TPB) local += g_partial[i];
        #pragma unroll
        for (int o = 16; o; o >>= 1) local += __shfl_down_sync(0xffffffffu, local, o);
        if ((tid & 31) == 0) s_warp[tid >> 5] = local;
        __syncthreads();
        if (tid < TPB/32) {
            double v = s_warp[tid];
            #pragma unroll
            for (int o = TPB/64; o; o >>= 1) v += __shfl_down_sync(0xffu, v, o);
            if (tid == 0) {
                double S0   = v + g_corr[0];                 // noobj bce sum
                double nobj = (double)g_nObj;
                double cnt  = (double)CELLS - (double)g_removed;
                double loss = (g_corr[2] + g_corr[3] + g_corr[4] + g_corr[5]
                               + g_corr[1] + g_corr[6] / (double)BB) / nobj
                            + S0 / cnt;
                out[0] = (float)loss;
            }
        }
    }
}

extern "C" void kernel_launch(void* const* d_in, const int* in_sizes, int n_in,
                              void* d_out, int out_size) {
    const float* x  = (const float*)d_in[0];
    const float* tg = (const float*)d_in[1];
    const float* an = (const float*)d_in[2];
    fused<<<NB_TOTAL, TPB>>>(x, tg, an, (float*)d_out);
}